// round 13
// baseline (speedup 1.0000x reference)
#include <cuda_runtime.h>
#include <cuda_fp16.h>
#include <cstdint>

#define BB 8
#define CC 64
#define CQ 8
#define NN 4096
#define KT 64
#define NSPLIT 2
#define KEYS_PER_SPLIT (NN / NSPLIT)          // 2048
#define TILES_PER_SPLIT (KEYS_PER_SPLIT / KT) // 32
#define LOG2E 1.4426950408889634f

// Device scratch (allocation-free rule)
__device__ float    g_Q[BB * NN * CQ];          // [b][n][cq] f32, pre-scaled by log2e
__device__ uint32_t g_Kt[BB * NN * CQ];         // [b][n]: 8 tf32 bits, pair-permuted (c,c+4)
__device__ __half   g_Vh[BB * CC * NN];         // [b][c][n] fp16 (V^T)
__device__ float    g_P[NSPLIT * BB * CC * NN]; // [s][b][c][i] unnormalized partials (16MB)
__device__ float    g_L[NSPLIT * BB * NN];      // [s][b][i] partial row sums

// ---------------------------------------------------------------------------
// PTX helpers (baseline compute_103-safe)
// ---------------------------------------------------------------------------
__device__ __forceinline__ uint32_t smem_u32(const void* p) {
    uint32_t a;
    asm("{ .reg .u64 t; cvta.to.shared.u64 t, %1; cvt.u32.u64 %0, t; }" : "=r"(a) : "l"(p));
    return a;
}
__device__ __forceinline__ uint32_t packh(float lo, float hi) {   // f16x2 {hi|lo}
    uint32_t r;
    asm("cvt.rn.f16x2.f32 %0, %1, %2;" : "=r"(r) : "f"(hi), "f"(lo));
    return r;
}
__device__ __forceinline__ uint32_t ex2h2(uint32_t x) {           // packed f16x2 exp2
    uint32_t y;
    asm("ex2.approx.f16x2 %0, %1;" : "=r"(y) : "r"(x));
    return y;
}
__device__ __forceinline__ uint32_t tf32c(float f) {
    uint32_t r;
    asm("cvt.rna.tf32.f32 %0, %1;" : "=r"(r) : "f"(f));
    return r;
}
#define LDSM4(r0, r1, r2, r3, a) \
    asm volatile("ldmatrix.sync.aligned.m8n8.x4.shared.b16 {%0,%1,%2,%3}, [%4];" \
        : "=r"(r0), "=r"(r1), "=r"(r2), "=r"(r3) : "r"(a))
#define LDS64(r0, r1, a) \
    asm volatile("ld.shared.v2.u32 {%0,%1}, [%2];" : "=r"(r0), "=r"(r1) : "r"(a))
#define LDS32(r0, a) \
    asm volatile("ld.shared.u32 %0, [%1];" : "=r"(r0) : "r"(a))

#define CP_ASYNC16(dst, src) \
    asm volatile("cp.async.ca.shared.global [%0], [%1], 16;" :: "r"(dst), "l"(src) : "memory")
#define CP_COMMIT() asm volatile("cp.async.commit_group;" ::: "memory")
#define CP_WAIT0()  asm volatile("cp.async.wait_group 0;" ::: "memory")
#define CP_WAIT1()  asm volatile("cp.async.wait_group 1;" ::: "memory")

// m16n8k8 tf32 MMA, C = 0
#define MMAT32_Z(d, a0, a1, a2, a3, b0, b1) \
    asm volatile("mma.sync.aligned.m16n8k8.row.col.f32.tf32.tf32.f32 " \
        "{%0,%1,%2,%3}, {%4,%5,%6,%7}, {%8,%9}, {%10,%10,%10,%10};" \
        : "=f"((d)[0]), "=f"((d)[1]), "=f"((d)[2]), "=f"((d)[3]) \
        : "r"(a0), "r"(a1), "r"(a2), "r"(a3), "r"(b0), "r"(b1), "f"(0.f))
// m16n8k8 tf32 MMA, accumulate in place
#define MMAT32(d, a0, a1, a2, a3, b0, b1) \
    asm volatile("mma.sync.aligned.m16n8k8.row.col.f32.tf32.tf32.f32 " \
        "{%0,%1,%2,%3}, {%4,%5,%6,%7}, {%8,%9}, {%0,%1,%2,%3};" \
        : "+f"((d)[0]), "+f"((d)[1]), "+f"((d)[2]), "+f"((d)[3]) \
        : "r"(a0), "r"(a1), "r"(a2), "r"(a3), "r"(b0), "r"(b1))
// m16n8k16 fp16 MMA (f32 accum), accumulate in place
#define MMAH16(d, a0, a1, a2, a3, b0, b1) \
    asm volatile("mma.sync.aligned.m16n8k16.row.col.f32.f16.f16.f32 " \
        "{%0,%1,%2,%3}, {%4,%5,%6,%7}, {%8,%9}, {%0,%1,%2,%3};" \
        : "+f"((d)[0]), "+f"((d)[1]), "+f"((d)[2]), "+f"((d)[3]) \
        : "r"(a0), "r"(a1), "r"(a2), "r"(a3), "r"(b0), "r"(b1))

// ---------------------------------------------------------------------------
// Kernel 1: projections on tensor cores (tf32).
// 256 thr = 8 warps; CTA covers 128 pixels (2 x-tiles). Weights staged ONCE
// per 128 px (was per 64) -> 28% fewer LDGSTS issues. grid (32, 8) = 256 CTAs.
// Dynamic smem: x 2 tiles @ 17408B | W 23040B = 57856B.
// Warps 0-3 -> x-tile 0, warps 4-7 -> x-tile 1 (same GEMM per group).
// ---------------------------------------------------------------------------
#define SX_TILE 17408
#define SW_OFF  (2 * SX_TILE)
#define SMEM_PROJ (SW_OFF + 80 * 288)

__global__ void __launch_bounds__(256, 3) proj_kernel(
    const float* __restrict__ x,
    const float* __restrict__ wq, const float* __restrict__ bq,
    const float* __restrict__ wk, const float* __restrict__ bk,
    const float* __restrict__ wv, const float* __restrict__ bv)
{
    extern __shared__ __align__(16) char smp[];

    const int tid  = threadIdx.x;
    const int lane = tid & 31;
    const int w    = tid >> 5;        // 0..7
    const int wg   = w & 3;           // warp within group
    const int tile = w >> 2;          // x-tile 0/1
    const int g    = lane >> 2;
    const int t4   = lane & 3;
    const int b    = blockIdx.y;
    const int n0   = blockIdx.x * 128;

    const uint32_t smb = smem_u32(smp);
    const uint32_t swb = smb + SW_OFF;

    // Stage x: 2 tiles x 1024 chunks = 2048 chunks, 8 per thread
    const float* xb = x + (size_t)b * CC * NN + n0;
    #pragma unroll
    for (int i = 0; i < 8; ++i) {
        const int c = i * 256 + tid;
        const int tl = c >> 10, wi = c & 1023;
        const int row = wi >> 4, off = wi & 15;
        CP_ASYNC16(smb + tl * SX_TILE + row * 272 + off * 16,
                   xb + (size_t)row * NN + tl * 64 + off * 4);
    }
    // Stage W: wv 1024 chunks + wq 128 + wk 128 = 1280 chunks, 5 per thread
    #pragma unroll
    for (int i = 0; i < 5; ++i) {
        const int c = i * 256 + tid;
        if (c < 1024) {
            const int row = c >> 4, off = c & 15;
            CP_ASYNC16(swb + row * 288 + off * 16, wv + row * 64 + off * 4);
        } else if (c < 1152) {
            const int c2 = c - 1024;
            const int row = c2 >> 4, off = c2 & 15;
            CP_ASYNC16(swb + (64 + row) * 288 + off * 16, wq + row * 64 + off * 4);
        } else {
            const int c3 = c - 1152;
            const int row = c3 >> 4, off = c3 & 15;
            CP_ASYNC16(swb + (72 + row) * 288 + off * 16, wk + row * 64 + off * 4);
        }
    }
    CP_COMMIT();

    // Accumulators init with bias
    float acc[2][5][4];
    #pragma unroll
    for (int mt = 0; mt < 4; ++mt) {
        const float bA = __ldg(bv + mt * 16 + g);
        const float bB = __ldg(bv + mt * 16 + 8 + g);
        #pragma unroll
        for (int n2 = 0; n2 < 2; ++n2) {
            acc[n2][mt][0] = bA; acc[n2][mt][1] = bA;
            acc[n2][mt][2] = bB; acc[n2][mt][3] = bB;
        }
    }
    {
        const float bA = __ldg(bq + g);
        const float bB = __ldg(bk + g);
        #pragma unroll
        for (int n2 = 0; n2 < 2; ++n2) {
            acc[n2][4][0] = bA; acc[n2][4][1] = bA;
            acc[n2][4][2] = bB; acc[n2][4][3] = bB;
        }
    }

    CP_WAIT0();
    __syncthreads();

    // GEMM: 8 k-steps x (5 m-tiles x 2 n-tiles) per warp
    const uint32_t waddr0 = swb + (uint32_t)g * 288 + (uint32_t)t4 * 8;
    const uint32_t xaddr0 = smb + tile * SX_TILE + (uint32_t)(2 * t4) * 272
                          + (uint32_t)((wg * 2) * 8 + g) * 4;
    #pragma unroll
    for (int kt = 0; kt < 8; ++kt) {
        uint32_t wa[5][4];
        #pragma unroll
        for (int mt = 0; mt < 5; ++mt) {
            LDS64(wa[mt][0], wa[mt][2], waddr0 + (uint32_t)(mt * 16) * 288 + kt * 32);
            LDS64(wa[mt][1], wa[mt][3], waddr0 + (uint32_t)(mt * 16 + 8) * 288 + kt * 32);
        }
        #pragma unroll
        for (int mt = 0; mt < 5; ++mt) {
            #pragma unroll
            for (int e = 0; e < 4; ++e) wa[mt][e] = tf32c(__uint_as_float(wa[mt][e]));
        }
        #pragma unroll
        for (int n2 = 0; n2 < 2; ++n2) {
            uint32_t b0, b1;
            LDS32(b0, xaddr0 + kt * (8 * 272) + n2 * 32);
            LDS32(b1, xaddr0 + kt * (8 * 272) + n2 * 32 + 272);
            b0 = tf32c(__uint_as_float(b0));
            b1 = tf32c(__uint_as_float(b1));
            #pragma unroll
            for (int mt = 0; mt < 5; ++mt)
                MMAT32(acc[n2][mt], wa[mt][0], wa[mt][1], wa[mt][2], wa[mt][3], b0, b1);
        }
    }

    // Epilogue
    const int kslot = 2 * (g & 3) + (g >> 2);
    #pragma unroll
    for (int n2 = 0; n2 < 2; ++n2) {
        const int px = tile * 64 + (wg * 2 + n2) * 8 + 2 * t4;
        #pragma unroll
        for (int mt = 0; mt < 4; ++mt) {
            const int coA = mt * 16 + g;
            const int coB = coA + 8;
            *(uint32_t*)(g_Vh + (size_t)b * CC * NN + (size_t)coA * NN + n0 + px) =
                packh(acc[n2][mt][0], acc[n2][mt][1]);
            *(uint32_t*)(g_Vh + (size_t)b * CC * NN + (size_t)coB * NN + n0 + px) =
                packh(acc[n2][mt][2], acc[n2][mt][3]);
        }
        const size_t base0 = ((size_t)b * NN + n0 + px) * CQ;
        const size_t base1 = base0 + CQ;
        g_Q[base0 + g] = acc[n2][4][0] * LOG2E;
        g_Q[base1 + g] = acc[n2][4][1] * LOG2E;
        g_Kt[base0 + kslot] = tf32c(acc[n2][4][2]);
        g_Kt[base1 + kslot] = tf32c(acc[n2][4][3]);
    }
}

// ---------------------------------------------------------------------------
// Kernel 2: fused attention, warp-M=32, split-K 2, fp16 PV + packed f16 exp.
// grid (32, 8, 2) = 512 CTAs @ occ 4 -> single full wave (592 slots).
// ---------------------------------------------------------------------------
__global__ void __launch_bounds__(128, 4) attn_kernel()
{
    __shared__ __align__(16) char smraw[6144 + 3 * 8192];

    const int tid  = threadIdx.x;
    const int lane = tid & 31;
    const int w    = tid >> 5;
    const int g    = lane >> 2;
    const int t4   = lane & 3;
    const int b    = blockIdx.y;
    const int s    = blockIdx.z;
    const int ibase = blockIdx.x * 128 + w * 32;

    const uint32_t smb = smem_u32(smraw);
    const uint32_t ONESH = 0x3C003C00u;       // f16x2 {1.0, 1.0}

    // Q A-fragments for 2 m-tiles
    const float* Qb = g_Q + (size_t)b * NN * CQ;
    uint32_t qa[2][4];
    #pragma unroll
    for (int mt = 0; mt < 2; ++mt) {
        const float* q0p = Qb + (size_t)(ibase + mt * 16 + g) * CQ;
        const float* q1p = Qb + (size_t)(ibase + mt * 16 + g + 8) * CQ;
        qa[mt][0] = tf32c(q0p[t4]);
        qa[mt][1] = tf32c(q1p[t4]);
        qa[mt][2] = tf32c(q0p[t4 + 4]);
        qa[mt][3] = tf32c(q1p[t4 + 4]);
    }

    // K staging (split-shifted)
    const uint32_t* Ksrc = g_Kt + (size_t)b * NN * CQ + (size_t)s * KEYS_PER_SPLIT * CQ
                         + (size_t)(tid >> 1) * 8 + (tid & 1) * 4;
    const uint32_t kdst = smb + (uint32_t)(tid >> 1) * 32 + (uint32_t)(tid & 1) * 16;

    // V staging (split-shifted)
    const char* Vgb = (const char*)(g_Vh + (size_t)b * CC * NN);
    const uint32_t voff0 = (uint32_t)(tid >> 3) * (NN * 2) + (uint32_t)(tid & 7) * 16
                         + (uint32_t)s * (KEYS_PER_SPLIT * 2);
    const uint32_t vdst0 = smb + 6144 + (uint32_t)(tid >> 3) * 128
                         + (uint32_t)(((tid & 7) ^ ((tid >> 3) & 7)) << 4);

    // Score B-fragment LDS address
    const uint32_t kfrag0 = smb + (uint32_t)(lane >> 2) * 32 + (uint32_t)t4 * 8;

    // V ldmatrix addresses
    const int mat = lane >> 3, mrow = lane & 7, m01 = mat & 1;
    const uint32_t vbase0 = smb + 6144 + (uint32_t)((mat >> 1) * 8 + mrow) * 128;

    // Prologue: tiles 0, 1 of this split
    #pragma unroll
    for (int t = 0; t < 2; ++t) {
        CP_ASYNC16(kdst + t * 2048, Ksrc + (size_t)t * KT * CQ);
        #pragma unroll
        for (int r = 0; r < 4; ++r)
            CP_ASYNC16(vdst0 + r * 2048 + t * 8192, Vgb + voff0 + r * 131072 + t * 128);
        CP_COMMIT();
    }

    float acc[2][8][4];
    #pragma unroll
    for (int mt = 0; mt < 2; ++mt)
        #pragma unroll
        for (int nb = 0; nb < 8; ++nb)
            #pragma unroll
            for (int e = 0; e < 4; ++e) acc[mt][nb][e] = 0.f;
    float lacc[2][4];
    #pragma unroll
    for (int mt = 0; mt < 2; ++mt)
        #pragma unroll
        for (int e = 0; e < 4; ++e) lacc[mt][e] = 0.f;
    uint32_t ksoff = 0, vsoff = 0;

    #pragma unroll 1
    for (int t = 0; t < TILES_PER_SPLIT; ++t) {
        CP_WAIT1();
        __syncthreads();

        // Prefetch tile t+2
        {
            const int tc = t + 2;
            uint32_t ks2 = ksoff + 4096;  if (ks2 >= 6144)  ks2 -= 6144;
            uint32_t vs2 = vsoff + 16384; if (vs2 >= 24576) vs2 -= 24576;
            if (tc < TILES_PER_SPLIT) {
                CP_ASYNC16(kdst + ks2, Ksrc + (size_t)tc * KT * CQ);
                #pragma unroll
                for (int r = 0; r < 4; ++r)
                    CP_ASYNC16(vdst0 + r * 2048 + vs2,
                               Vgb + voff0 + r * 131072 + (size_t)tc * 128);
            }
            CP_COMMIT();
        }

        #pragma unroll
        for (int kt = 0; kt < 4; ++kt) {
            // K b-fragments (shared by both m-tiles)
            uint32_t b00, b01, b10, b11;
            LDS64(b00, b01, kfrag0 + ksoff + (uint32_t)(2 * kt) * 256);
            LDS64(b10, b11, kfrag0 + ksoff + (uint32_t)(2 * kt) * 256 + 256);

            // Scores for 2 m-tiles x 2 n-tiles
            float p[2][2][4];
            #pragma unroll
            for (int mt = 0; mt < 2; ++mt) {
                MMAT32_Z(p[mt][0], qa[mt][0], qa[mt][1], qa[mt][2], qa[mt][3], b00, b01);
                MMAT32_Z(p[mt][1], qa[mt][0], qa[mt][1], qa[mt][2], qa[mt][3], b10, b11);
            }

            // Pack score pairs to f16x2, packed exp2 -> A-fragments directly
            uint32_t a[2][4];
            #pragma unroll
            for (int mt = 0; mt < 2; ++mt) {
                a[mt][0] = ex2h2(packh(p[mt][0][0], p[mt][0][1]));
                a[mt][1] = ex2h2(packh(p[mt][0][2], p[mt][0][3]));
                a[mt][2] = ex2h2(packh(p[mt][1][0], p[mt][1][1]));
                a[mt][3] = ex2h2(packh(p[mt][1][2], p[mt][1][3]));
            }

            // V b-fragments (shared by both m-tiles)
            const uint32_t term = ((uint32_t)((2 * kt + m01) ^ mrow)) << 4;
            uint32_t vb[16];
            #pragma unroll
            for (int c = 0; c < 4; ++c)
                LDSM4(vb[4 * c + 0], vb[4 * c + 1], vb[4 * c + 2], vb[4 * c + 3],
                      vbase0 + vsoff + c * 2048 + term);
            #pragma unroll
            for (int mt = 0; mt < 2; ++mt) {
                #pragma unroll
                for (int nb = 0; nb < 8; ++nb)
                    MMAH16(acc[mt][nb], a[mt][0], a[mt][1], a[mt][2], a[mt][3],
                           vb[2 * nb], vb[2 * nb + 1]);
                // l row-sums on tensor pipe (exact f32)
                MMAH16(lacc[mt], a[mt][0], a[mt][1], a[mt][2], a[mt][3], ONESH, ONESH);
            }
        }

        ksoff += 2048; if (ksoff == 6144)  ksoff = 0;
        vsoff += 8192; if (vsoff == 24576) vsoff = 0;
    }

    // Write unnormalized partials
    float* Pb = g_P + ((size_t)(s * BB + b) * CC) * NN;
    #pragma unroll
    for (int mt = 0; mt < 2; ++mt) {
        const int rA = ibase + mt * 16 + g;
        const int rB = rA + 8;
        #pragma unroll
        for (int nb = 0; nb < 8; ++nb) {
            const int c = nb * 8 + 2 * t4;
            Pb[(size_t)c * NN + rA]       = acc[mt][nb][0];
            Pb[(size_t)(c + 1) * NN + rA] = acc[mt][nb][1];
            Pb[(size_t)c * NN + rB]       = acc[mt][nb][2];
            Pb[(size_t)(c + 1) * NN + rB] = acc[mt][nb][3];
        }
    }
    if (t4 == 0) {
        float* Lb = g_L + (size_t)(s * BB + b) * NN;
        #pragma unroll
        for (int mt = 0; mt < 2; ++mt) {
            Lb[ibase + mt * 16 + g]     = lacc[mt][0];
            Lb[ibase + mt * 16 + g + 8] = lacc[mt][2];
        }
    }
}

// ---------------------------------------------------------------------------
// Kernel 3: combine split-K partials. out = sum_s P_s / sum_s L_s.
// ---------------------------------------------------------------------------
__global__ void __launch_bounds__(256) reduce_kernel(float* __restrict__ out)
{
    const int idx = blockIdx.x * 256 + threadIdx.x;
    const int i4  = idx & 1023;
    const int bc  = idx >> 10;
    const int b   = bc >> 6;

    const float4* P4 = (const float4*)g_P;
    const float4* L4 = (const float4*)g_L;

    float4 ps = make_float4(0.f, 0.f, 0.f, 0.f);
    float4 ls = make_float4(0.f, 0.f, 0.f, 0.f);
    #pragma unroll
    for (int s = 0; s < NSPLIT; ++s) {
        const float4 p = P4[(size_t)(s * (BB * CC) + bc) * 1024 + i4];
        const float4 l = L4[(size_t)(s * BB + b) * 1024 + i4];
        ps.x += p.x; ps.y += p.y; ps.z += p.z; ps.w += p.w;
        ls.x += l.x; ls.y += l.y; ls.z += l.z; ls.w += l.w;
    }
    float4 o;
    o.x = ps.x / ls.x;
    o.y = ps.y / ls.y;
    o.z = ps.z / ls.z;
    o.w = ps.w / ls.w;
    ((float4*)out)[(size_t)bc * 1024 + i4] = o;
}

// ---------------------------------------------------------------------------
extern "C" void kernel_launch(void* const* d_in, const int* in_sizes, int n_in,
                              void* d_out, int out_size)
{
    const float* x  = (const float*)d_in[0];
    const float* wq = (const float*)d_in[1];
    const float* bq = (const float*)d_in[2];
    const float* wk = (const float*)d_in[3];
    const float* bk = (const float*)d_in[4];
    const float* wv = (const float*)d_in[5];
    const float* bv = (const float*)d_in[6];
    float* out = (float*)d_out;

    cudaFuncSetAttribute(proj_kernel, cudaFuncAttributeMaxDynamicSharedMemorySize, SMEM_PROJ);

    dim3 pgrid(NN / 128, BB);
    proj_kernel<<<pgrid, 256, SMEM_PROJ>>>(x, wq, bq, wk, bk, wv, bv);

    dim3 agrid(NN / 128, BB, NSPLIT);
    attn_kernel<<<agrid, 128>>>();

    reduce_kernel<<<2048, 256>>>(out);
}

// round 14
// speedup vs baseline: 1.0583x; 1.0583x over previous
#include <cuda_runtime.h>
#include <cuda_fp16.h>
#include <cstdint>

#define BB 8
#define CC 64
#define CQ 8
#define NN 4096
#define KT 64
#define NSPLIT 4
#define KEYS_PER_SPLIT (NN / NSPLIT)          // 1024
#define TILES_PER_SPLIT (KEYS_PER_SPLIT / KT) // 16
#define LOG2E 1.4426950408889634f

// Device scratch (allocation-free rule)
__device__ float    g_Q[BB * NN * CQ];          // [b][n][cq] f32, pre-scaled by log2e
__device__ uint32_t g_Kt[BB * NN * CQ];         // [b][n]: 8 tf32 bits, pair-permuted (c,c+4)
__device__ __half   g_Vh[BB * CC * NN];         // [b][c][n] fp16 (V^T)
__device__ __half   g_P[NSPLIT * BB * CC * NN]; // [s][b][c][i] fp16 partials (16MB)
__device__ float    g_L[NSPLIT * BB * NN];      // [s][b][i] partial row sums (f32)

// ---------------------------------------------------------------------------
// PTX helpers (baseline compute_103-safe)
// ---------------------------------------------------------------------------
__device__ __forceinline__ uint32_t smem_u32(const void* p) {
    uint32_t a;
    asm("{ .reg .u64 t; cvta.to.shared.u64 t, %1; cvt.u32.u64 %0, t; }" : "=r"(a) : "l"(p));
    return a;
}
__device__ __forceinline__ uint32_t packh(float lo, float hi) {   // f16x2 {hi|lo}
    uint32_t r;
    asm("cvt.rn.f16x2.f32 %0, %1, %2;" : "=r"(r) : "f"(hi), "f"(lo));
    return r;
}
__device__ __forceinline__ uint32_t ex2h2(uint32_t x) {           // packed f16x2 exp2
    uint32_t y;
    asm("ex2.approx.f16x2 %0, %1;" : "=r"(y) : "r"(x));
    return y;
}
__device__ __forceinline__ uint32_t tf32c(float f) {
    uint32_t r;
    asm("cvt.rna.tf32.f32 %0, %1;" : "=r"(r) : "f"(f));
    return r;
}
#define LDSM4(r0, r1, r2, r3, a) \
    asm volatile("ldmatrix.sync.aligned.m8n8.x4.shared.b16 {%0,%1,%2,%3}, [%4];" \
        : "=r"(r0), "=r"(r1), "=r"(r2), "=r"(r3) : "r"(a))
#define LDS64(r0, r1, a) \
    asm volatile("ld.shared.v2.u32 {%0,%1}, [%2];" : "=r"(r0), "=r"(r1) : "r"(a))
#define LDS32(r0, a) \
    asm volatile("ld.shared.u32 %0, [%1];" : "=r"(r0) : "r"(a))

#define CP_ASYNC16(dst, src) \
    asm volatile("cp.async.ca.shared.global [%0], [%1], 16;" :: "r"(dst), "l"(src) : "memory")
#define CP_COMMIT() asm volatile("cp.async.commit_group;" ::: "memory")
#define CP_WAIT0()  asm volatile("cp.async.wait_group 0;" ::: "memory")
#define CP_WAIT1()  asm volatile("cp.async.wait_group 1;" ::: "memory")

// m16n8k8 tf32 MMA, C = 0
#define MMAT32_Z(d, a0, a1, a2, a3, b0, b1) \
    asm volatile("mma.sync.aligned.m16n8k8.row.col.f32.tf32.tf32.f32 " \
        "{%0,%1,%2,%3}, {%4,%5,%6,%7}, {%8,%9}, {%10,%10,%10,%10};" \
        : "=f"((d)[0]), "=f"((d)[1]), "=f"((d)[2]), "=f"((d)[3]) \
        : "r"(a0), "r"(a1), "r"(a2), "r"(a3), "r"(b0), "r"(b1), "f"(0.f))
// m16n8k8 tf32 MMA, accumulate in place
#define MMAT32(d, a0, a1, a2, a3, b0, b1) \
    asm volatile("mma.sync.aligned.m16n8k8.row.col.f32.tf32.tf32.f32 " \
        "{%0,%1,%2,%3}, {%4,%5,%6,%7}, {%8,%9}, {%0,%1,%2,%3};" \
        : "+f"((d)[0]), "+f"((d)[1]), "+f"((d)[2]), "+f"((d)[3]) \
        : "r"(a0), "r"(a1), "r"(a2), "r"(a3), "r"(b0), "r"(b1))
// m16n8k16 fp16 MMA (f32 accum), accumulate in place
#define MMAH16(d, a0, a1, a2, a3, b0, b1) \
    asm volatile("mma.sync.aligned.m16n8k16.row.col.f32.f16.f16.f32 " \
        "{%0,%1,%2,%3}, {%4,%5,%6,%7}, {%8,%9}, {%0,%1,%2,%3};" \
        : "+f"((d)[0]), "+f"((d)[1]), "+f"((d)[2]), "+f"((d)[3]) \
        : "r"(a0), "r"(a1), "r"(a2), "r"(a3), "r"(b0), "r"(b1))

// ---------------------------------------------------------------------------
// Kernel 1: projections on tensor cores (tf32) — round-13 version (9.7us).
// 256 thr = 8 warps; CTA covers 128 pixels (2 x-tiles); weights staged once.
// ---------------------------------------------------------------------------
#define SX_TILE 17408
#define SW_OFF  (2 * SX_TILE)
#define SMEM_PROJ (SW_OFF + 80 * 288)

__global__ void __launch_bounds__(256, 3) proj_kernel(
    const float* __restrict__ x,
    const float* __restrict__ wq, const float* __restrict__ bq,
    const float* __restrict__ wk, const float* __restrict__ bk,
    const float* __restrict__ wv, const float* __restrict__ bv)
{
    extern __shared__ __align__(16) char smp[];

    const int tid  = threadIdx.x;
    const int lane = tid & 31;
    const int w    = tid >> 5;
    const int wg   = w & 3;
    const int tile = w >> 2;
    const int g    = lane >> 2;
    const int t4   = lane & 3;
    const int b    = blockIdx.y;
    const int n0   = blockIdx.x * 128;

    const uint32_t smb = smem_u32(smp);
    const uint32_t swb = smb + SW_OFF;

    const float* xb = x + (size_t)b * CC * NN + n0;
    #pragma unroll
    for (int i = 0; i < 8; ++i) {
        const int c = i * 256 + tid;
        const int tl = c >> 10, wi = c & 1023;
        const int row = wi >> 4, off = wi & 15;
        CP_ASYNC16(smb + tl * SX_TILE + row * 272 + off * 16,
                   xb + (size_t)row * NN + tl * 64 + off * 4);
    }
    #pragma unroll
    for (int i = 0; i < 5; ++i) {
        const int c = i * 256 + tid;
        if (c < 1024) {
            const int row = c >> 4, off = c & 15;
            CP_ASYNC16(swb + row * 288 + off * 16, wv + row * 64 + off * 4);
        } else if (c < 1152) {
            const int c2 = c - 1024;
            const int row = c2 >> 4, off = c2 & 15;
            CP_ASYNC16(swb + (64 + row) * 288 + off * 16, wq + row * 64 + off * 4);
        } else {
            const int c3 = c - 1152;
            const int row = c3 >> 4, off = c3 & 15;
            CP_ASYNC16(swb + (72 + row) * 288 + off * 16, wk + row * 64 + off * 4);
        }
    }
    CP_COMMIT();

    float acc[2][5][4];
    #pragma unroll
    for (int mt = 0; mt < 4; ++mt) {
        const float bA = __ldg(bv + mt * 16 + g);
        const float bB = __ldg(bv + mt * 16 + 8 + g);
        #pragma unroll
        for (int n2 = 0; n2 < 2; ++n2) {
            acc[n2][mt][0] = bA; acc[n2][mt][1] = bA;
            acc[n2][mt][2] = bB; acc[n2][mt][3] = bB;
        }
    }
    {
        const float bA = __ldg(bq + g);
        const float bB = __ldg(bk + g);
        #pragma unroll
        for (int n2 = 0; n2 < 2; ++n2) {
            acc[n2][4][0] = bA; acc[n2][4][1] = bA;
            acc[n2][4][2] = bB; acc[n2][4][3] = bB;
        }
    }

    CP_WAIT0();
    __syncthreads();

    const uint32_t waddr0 = swb + (uint32_t)g * 288 + (uint32_t)t4 * 8;
    const uint32_t xaddr0 = smb + tile * SX_TILE + (uint32_t)(2 * t4) * 272
                          + (uint32_t)((wg * 2) * 8 + g) * 4;
    #pragma unroll
    for (int kt = 0; kt < 8; ++kt) {
        uint32_t wa[5][4];
        #pragma unroll
        for (int mt = 0; mt < 5; ++mt) {
            LDS64(wa[mt][0], wa[mt][2], waddr0 + (uint32_t)(mt * 16) * 288 + kt * 32);
            LDS64(wa[mt][1], wa[mt][3], waddr0 + (uint32_t)(mt * 16 + 8) * 288 + kt * 32);
        }
        #pragma unroll
        for (int mt = 0; mt < 5; ++mt) {
            #pragma unroll
            for (int e = 0; e < 4; ++e) wa[mt][e] = tf32c(__uint_as_float(wa[mt][e]));
        }
        #pragma unroll
        for (int n2 = 0; n2 < 2; ++n2) {
            uint32_t b0, b1;
            LDS32(b0, xaddr0 + kt * (8 * 272) + n2 * 32);
            LDS32(b1, xaddr0 + kt * (8 * 272) + n2 * 32 + 272);
            b0 = tf32c(__uint_as_float(b0));
            b1 = tf32c(__uint_as_float(b1));
            #pragma unroll
            for (int mt = 0; mt < 5; ++mt)
                MMAT32(acc[n2][mt], wa[mt][0], wa[mt][1], wa[mt][2], wa[mt][3], b0, b1);
        }
    }

    const int kslot = 2 * (g & 3) + (g >> 2);
    #pragma unroll
    for (int n2 = 0; n2 < 2; ++n2) {
        const int px = tile * 64 + (wg * 2 + n2) * 8 + 2 * t4;
        #pragma unroll
        for (int mt = 0; mt < 4; ++mt) {
            const int coA = mt * 16 + g;
            const int coB = coA + 8;
            *(uint32_t*)(g_Vh + (size_t)b * CC * NN + (size_t)coA * NN + n0 + px) =
                packh(acc[n2][mt][0], acc[n2][mt][1]);
            *(uint32_t*)(g_Vh + (size_t)b * CC * NN + (size_t)coB * NN + n0 + px) =
                packh(acc[n2][mt][2], acc[n2][mt][3]);
        }
        const size_t base0 = ((size_t)b * NN + n0 + px) * CQ;
        const size_t base1 = base0 + CQ;
        g_Q[base0 + g] = acc[n2][4][0] * LOG2E;
        g_Q[base1 + g] = acc[n2][4][1] * LOG2E;
        g_Kt[base0 + kslot] = tf32c(acc[n2][4][2]);
        g_Kt[base1 + kslot] = tf32c(acc[n2][4][3]);
    }
}

// ---------------------------------------------------------------------------
// Kernel 2: fused attention — round-12 config (occ 3, NSPLIT 4), fp16 partials.
// Block = 128 thr = 4 warps x 32 query rows. grid (32, 8, 4) = 1024 CTAs.
// ---------------------------------------------------------------------------
__global__ void __launch_bounds__(128, 3) attn_kernel()
{
    __shared__ __align__(16) char smraw[6144 + 3 * 8192];

    const int tid  = threadIdx.x;
    const int lane = tid & 31;
    const int w    = tid >> 5;
    const int g    = lane >> 2;
    const int t4   = lane & 3;
    const int b    = blockIdx.y;
    const int s    = blockIdx.z;
    const int ibase = blockIdx.x * 128 + w * 32;

    const uint32_t smb = smem_u32(smraw);
    const uint32_t ONESH = 0x3C003C00u;       // f16x2 {1.0, 1.0}

    // Q A-fragments for 2 m-tiles
    const float* Qb = g_Q + (size_t)b * NN * CQ;
    uint32_t qa[2][4];
    #pragma unroll
    for (int mt = 0; mt < 2; ++mt) {
        const float* q0p = Qb + (size_t)(ibase + mt * 16 + g) * CQ;
        const float* q1p = Qb + (size_t)(ibase + mt * 16 + g + 8) * CQ;
        qa[mt][0] = tf32c(q0p[t4]);
        qa[mt][1] = tf32c(q1p[t4]);
        qa[mt][2] = tf32c(q0p[t4 + 4]);
        qa[mt][3] = tf32c(q1p[t4 + 4]);
    }

    // K staging (split-shifted)
    const uint32_t* Ksrc = g_Kt + (size_t)b * NN * CQ + (size_t)s * KEYS_PER_SPLIT * CQ
                         + (size_t)(tid >> 1) * 8 + (tid & 1) * 4;
    const uint32_t kdst = smb + (uint32_t)(tid >> 1) * 32 + (uint32_t)(tid & 1) * 16;

    // V staging (split-shifted)
    const char* Vgb = (const char*)(g_Vh + (size_t)b * CC * NN);
    const uint32_t voff0 = (uint32_t)(tid >> 3) * (NN * 2) + (uint32_t)(tid & 7) * 16
                         + (uint32_t)s * (KEYS_PER_SPLIT * 2);
    const uint32_t vdst0 = smb + 6144 + (uint32_t)(tid >> 3) * 128
                         + (uint32_t)(((tid & 7) ^ ((tid >> 3) & 7)) << 4);

    // Score B-fragment LDS address
    const uint32_t kfrag0 = smb + (uint32_t)(lane >> 2) * 32 + (uint32_t)t4 * 8;

    // V ldmatrix addresses
    const int mat = lane >> 3, mrow = lane & 7, m01 = mat & 1;
    const uint32_t vbase0 = smb + 6144 + (uint32_t)((mat >> 1) * 8 + mrow) * 128;

    // Prologue: tiles 0, 1 of this split
    #pragma unroll
    for (int t = 0; t < 2; ++t) {
        CP_ASYNC16(kdst + t * 2048, Ksrc + (size_t)t * KT * CQ);
        #pragma unroll
        for (int r = 0; r < 4; ++r)
            CP_ASYNC16(vdst0 + r * 2048 + t * 8192, Vgb + voff0 + r * 131072 + t * 128);
        CP_COMMIT();
    }

    float acc[2][8][4];
    #pragma unroll
    for (int mt = 0; mt < 2; ++mt)
        #pragma unroll
        for (int nb = 0; nb < 8; ++nb)
            #pragma unroll
            for (int e = 0; e < 4; ++e) acc[mt][nb][e] = 0.f;
    float lacc[2][4];
    #pragma unroll
    for (int mt = 0; mt < 2; ++mt)
        #pragma unroll
        for (int e = 0; e < 4; ++e) lacc[mt][e] = 0.f;
    uint32_t ksoff = 0, vsoff = 0;

    #pragma unroll 1
    for (int t = 0; t < TILES_PER_SPLIT; ++t) {
        CP_WAIT1();
        __syncthreads();

        // Prefetch tile t+2
        {
            const int tc = t + 2;
            uint32_t ks2 = ksoff + 4096;  if (ks2 >= 6144)  ks2 -= 6144;
            uint32_t vs2 = vsoff + 16384; if (vs2 >= 24576) vs2 -= 24576;
            if (tc < TILES_PER_SPLIT) {
                CP_ASYNC16(kdst + ks2, Ksrc + (size_t)tc * KT * CQ);
                #pragma unroll
                for (int r = 0; r < 4; ++r)
                    CP_ASYNC16(vdst0 + r * 2048 + vs2,
                               Vgb + voff0 + r * 131072 + (size_t)tc * 128);
            }
            CP_COMMIT();
        }

        #pragma unroll
        for (int kt = 0; kt < 4; ++kt) {
            uint32_t b00, b01, b10, b11;
            LDS64(b00, b01, kfrag0 + ksoff + (uint32_t)(2 * kt) * 256);
            LDS64(b10, b11, kfrag0 + ksoff + (uint32_t)(2 * kt) * 256 + 256);

            float p[2][2][4];
            #pragma unroll
            for (int mt = 0; mt < 2; ++mt) {
                MMAT32_Z(p[mt][0], qa[mt][0], qa[mt][1], qa[mt][2], qa[mt][3], b00, b01);
                MMAT32_Z(p[mt][1], qa[mt][0], qa[mt][1], qa[mt][2], qa[mt][3], b10, b11);
            }

            uint32_t a[2][4];
            #pragma unroll
            for (int mt = 0; mt < 2; ++mt) {
                a[mt][0] = ex2h2(packh(p[mt][0][0], p[mt][0][1]));
                a[mt][1] = ex2h2(packh(p[mt][0][2], p[mt][0][3]));
                a[mt][2] = ex2h2(packh(p[mt][1][0], p[mt][1][1]));
                a[mt][3] = ex2h2(packh(p[mt][1][2], p[mt][1][3]));
            }

            const uint32_t term = ((uint32_t)((2 * kt + m01) ^ mrow)) << 4;
            uint32_t vb[16];
            #pragma unroll
            for (int c = 0; c < 4; ++c)
                LDSM4(vb[4 * c + 0], vb[4 * c + 1], vb[4 * c + 2], vb[4 * c + 3],
                      vbase0 + vsoff + c * 2048 + term);
            #pragma unroll
            for (int mt = 0; mt < 2; ++mt) {
                #pragma unroll
                for (int nb = 0; nb < 8; ++nb)
                    MMAH16(acc[mt][nb], a[mt][0], a[mt][1], a[mt][2], a[mt][3],
                           vb[2 * nb], vb[2 * nb + 1]);
                MMAH16(lacc[mt], a[mt][0], a[mt][1], a[mt][2], a[mt][3], ONESH, ONESH);
            }
        }

        ksoff += 2048; if (ksoff == 6144)  ksoff = 0;
        vsoff += 8192; if (vsoff == 24576) vsoff = 0;
    }

    // Write unnormalized fp16 partials
    __half* Pb = g_P + ((size_t)(s * BB + b) * CC) * NN;
    #pragma unroll
    for (int mt = 0; mt < 2; ++mt) {
        const int rA = ibase + mt * 16 + g;
        const int rB = rA + 8;
        #pragma unroll
        for (int nb = 0; nb < 8; ++nb) {
            const int c = nb * 8 + 2 * t4;
            Pb[(size_t)c * NN + rA]       = __float2half(acc[mt][nb][0]);
            Pb[(size_t)(c + 1) * NN + rA] = __float2half(acc[mt][nb][1]);
            Pb[(size_t)c * NN + rB]       = __float2half(acc[mt][nb][2]);
            Pb[(size_t)(c + 1) * NN + rB] = __float2half(acc[mt][nb][3]);
        }
    }
    if (t4 == 0) {
        float* Lb = g_L + (size_t)(s * BB + b) * NN;
        #pragma unroll
        for (int mt = 0; mt < 2; ++mt) {
            Lb[ibase + mt * 16 + g]     = lacc[mt][0];
            Lb[ibase + mt * 16 + g + 8] = lacc[mt][2];
        }
    }
}

// ---------------------------------------------------------------------------
// Kernel 3: combine split-K fp16 partials. out = sum_s P_s / sum_s L_s.
// Each thread handles 8 consecutive i (one uint4 of halfs per split).
// 262144 threads -> 1024 blocks x 256.
// ---------------------------------------------------------------------------
__global__ void __launch_bounds__(256) reduce_kernel(float* __restrict__ out)
{
    const int idx = blockIdx.x * 256 + threadIdx.x;
    const int i8  = idx & 511;                 // 4096/8 chunks per (b,c) row
    const int bc  = idx >> 9;                  // b*64 + c
    const int b   = bc >> 6;

    float ps[8] = {0.f, 0.f, 0.f, 0.f, 0.f, 0.f, 0.f, 0.f};
    float ls[8] = {0.f, 0.f, 0.f, 0.f, 0.f, 0.f, 0.f, 0.f};

    #pragma unroll
    for (int s = 0; s < NSPLIT; ++s) {
        const uint4 pw = *(const uint4*)(g_P + ((size_t)(s * (BB * CC) + bc)) * NN + i8 * 8);
        const uint32_t pk[4] = {pw.x, pw.y, pw.z, pw.w};
        #pragma unroll
        for (int j = 0; j < 4; ++j) {
            const float2 f = __half22float2(*(const __half2*)&pk[j]);
            ps[2 * j + 0] += f.x;
            ps[2 * j + 1] += f.y;
        }
        const float4* Lp = (const float4*)(g_L + (size_t)(s * BB + b) * NN + i8 * 8);
        const float4 l0 = Lp[0];
        const float4 l1 = Lp[1];
        ls[0] += l0.x; ls[1] += l0.y; ls[2] += l0.z; ls[3] += l0.w;
        ls[4] += l1.x; ls[5] += l1.y; ls[6] += l1.z; ls[7] += l1.w;
    }

    float4* op = (float4*)(out + (size_t)bc * NN + i8 * 8);
    op[0] = make_float4(ps[0] / ls[0], ps[1] / ls[1], ps[2] / ls[2], ps[3] / ls[3]);
    op[1] = make_float4(ps[4] / ls[4], ps[5] / ls[5], ps[6] / ls[6], ps[7] / ls[7]);
}

// ---------------------------------------------------------------------------
extern "C" void kernel_launch(void* const* d_in, const int* in_sizes, int n_in,
                              void* d_out, int out_size)
{
    const float* x  = (const float*)d_in[0];
    const float* wq = (const float*)d_in[1];
    const float* bq = (const float*)d_in[2];
    const float* wk = (const float*)d_in[3];
    const float* bk = (const float*)d_in[4];
    const float* wv = (const float*)d_in[5];
    const float* bv = (const float*)d_in[6];
    float* out = (float*)d_out;

    cudaFuncSetAttribute(proj_kernel, cudaFuncAttributeMaxDynamicSharedMemorySize, SMEM_PROJ);

    dim3 pgrid(NN / 128, BB);
    proj_kernel<<<pgrid, 256, SMEM_PROJ>>>(x, wq, bq, wk, bk, wv, bv);

    dim3 agrid(NN / 128, BB, NSPLIT);
    attn_kernel<<<agrid, 128>>>();

    reduce_kernel<<<1024, 256>>>(out);
}

// round 15
// speedup vs baseline: 1.1163x; 1.0547x over previous
#include <cuda_runtime.h>
#include <cuda_fp16.h>
#include <cstdint>

#define BB 8
#define CC 64
#define CQ 8
#define NN 4096
#define KT 64
#define NSPLIT 4
#define KEYS_PER_SPLIT (NN / NSPLIT)          // 1024
#define TILES_PER_SPLIT (KEYS_PER_SPLIT / KT) // 16
#define LOG2E 1.4426950408889634f

// Device scratch (allocation-free rule)
__device__ float    g_Q[BB * NN * CQ];          // [b][n][cq] f32, pre-scaled by log2e
__device__ uint32_t g_Kt[BB * NN * CQ];         // [b][n]: 8 tf32 bits, pair-permuted (c,c+4)
__device__ __half   g_Vh[BB * CC * NN];         // [b][c][n] fp16 (V^T)
__device__ float    g_P[NSPLIT * BB * CC * NN]; // [s][b][c][i] f32 partials (32MB)
__device__ float    g_L[NSPLIT * BB * NN];      // [s][b][i] partial row sums (f32)

// ---------------------------------------------------------------------------
// PTX helpers (baseline compute_103-safe)
// ---------------------------------------------------------------------------
__device__ __forceinline__ uint32_t smem_u32(const void* p) {
    uint32_t a;
    asm("{ .reg .u64 t; cvta.to.shared.u64 t, %1; cvt.u32.u64 %0, t; }" : "=r"(a) : "l"(p));
    return a;
}
__device__ __forceinline__ uint32_t packh(float lo, float hi) {   // f16x2 {hi|lo}
    uint32_t r;
    asm("cvt.rn.f16x2.f32 %0, %1, %2;" : "=r"(r) : "f"(hi), "f"(lo));
    return r;
}
__device__ __forceinline__ uint32_t ex2h2(uint32_t x) {           // packed f16x2 exp2
    uint32_t y;
    asm("ex2.approx.f16x2 %0, %1;" : "=r"(y) : "r"(x));
    return y;
}
__device__ __forceinline__ uint32_t hadd2(uint32_t a, uint32_t b) {
    uint32_t r;
    asm("add.f16x2 %0, %1, %2;" : "=r"(r) : "r"(a), "r"(b));
    return r;
}
__device__ __forceinline__ uint32_t tf32c(float f) {
    uint32_t r;
    asm("cvt.rna.tf32.f32 %0, %1;" : "=r"(r) : "f"(f));
    return r;
}
#define LDSM4(r0, r1, r2, r3, a) \
    asm volatile("ldmatrix.sync.aligned.m8n8.x4.shared.b16 {%0,%1,%2,%3}, [%4];" \
        : "=r"(r0), "=r"(r1), "=r"(r2), "=r"(r3) : "r"(a))
#define LDS64(r0, r1, a) \
    asm volatile("ld.shared.v2.u32 {%0,%1}, [%2];" : "=r"(r0), "=r"(r1) : "r"(a))
#define LDS32(r0, a) \
    asm volatile("ld.shared.u32 %0, [%1];" : "=r"(r0) : "r"(a))

#define CP_ASYNC16(dst, src) \
    asm volatile("cp.async.ca.shared.global [%0], [%1], 16;" :: "r"(dst), "l"(src) : "memory")
#define CP_COMMIT() asm volatile("cp.async.commit_group;" ::: "memory")
#define CP_WAIT0()  asm volatile("cp.async.wait_group 0;" ::: "memory")
#define CP_WAIT1()  asm volatile("cp.async.wait_group 1;" ::: "memory")

// m16n8k8 tf32 MMA, C = 0
#define MMAT32_Z(d, a0, a1, a2, a3, b0, b1) \
    asm volatile("mma.sync.aligned.m16n8k8.row.col.f32.tf32.tf32.f32 " \
        "{%0,%1,%2,%3}, {%4,%5,%6,%7}, {%8,%9}, {%10,%10,%10,%10};" \
        : "=f"((d)[0]), "=f"((d)[1]), "=f"((d)[2]), "=f"((d)[3]) \
        : "r"(a0), "r"(a1), "r"(a2), "r"(a3), "r"(b0), "r"(b1), "f"(0.f))
// m16n8k8 tf32 MMA, accumulate in place
#define MMAT32(d, a0, a1, a2, a3, b0, b1) \
    asm volatile("mma.sync.aligned.m16n8k8.row.col.f32.tf32.tf32.f32 " \
        "{%0,%1,%2,%3}, {%4,%5,%6,%7}, {%8,%9}, {%0,%1,%2,%3};" \
        : "+f"((d)[0]), "+f"((d)[1]), "+f"((d)[2]), "+f"((d)[3]) \
        : "r"(a0), "r"(a1), "r"(a2), "r"(a3), "r"(b0), "r"(b1))
// m16n8k16 fp16 MMA (f32 accum), accumulate in place
#define MMAH16(d, a0, a1, a2, a3, b0, b1) \
    asm volatile("mma.sync.aligned.m16n8k16.row.col.f32.f16.f16.f32 " \
        "{%0,%1,%2,%3}, {%4,%5,%6,%7}, {%8,%9}, {%0,%1,%2,%3};" \
        : "+f"((d)[0]), "+f"((d)[1]), "+f"((d)[2]), "+f"((d)[3]) \
        : "r"(a0), "r"(a1), "r"(a2), "r"(a3), "r"(b0), "r"(b1))

// ---------------------------------------------------------------------------
// Kernel 1: projections on tensor cores (tf32) — round-13/14 version (9.6us).
// 256 thr = 8 warps; CTA covers 128 pixels (2 x-tiles); weights staged once.
// ---------------------------------------------------------------------------
#define SX_TILE 17408
#define SW_OFF  (2 * SX_TILE)
#define SMEM_PROJ (SW_OFF + 80 * 288)

__global__ void __launch_bounds__(256, 3) proj_kernel(
    const float* __restrict__ x,
    const float* __restrict__ wq, const float* __restrict__ bq,
    const float* __restrict__ wk, const float* __restrict__ bk,
    const float* __restrict__ wv, const float* __restrict__ bv)
{
    extern __shared__ __align__(16) char smp[];

    const int tid  = threadIdx.x;
    const int lane = tid & 31;
    const int w    = tid >> 5;
    const int wg   = w & 3;
    const int tile = w >> 2;
    const int g    = lane >> 2;
    const int t4   = lane & 3;
    const int b    = blockIdx.y;
    const int n0   = blockIdx.x * 128;

    const uint32_t smb = smem_u32(smp);
    const uint32_t swb = smb + SW_OFF;

    const float* xb = x + (size_t)b * CC * NN + n0;
    #pragma unroll
    for (int i = 0; i < 8; ++i) {
        const int c = i * 256 + tid;
        const int tl = c >> 10, wi = c & 1023;
        const int row = wi >> 4, off = wi & 15;
        CP_ASYNC16(smb + tl * SX_TILE + row * 272 + off * 16,
                   xb + (size_t)row * NN + tl * 64 + off * 4);
    }
    #pragma unroll
    for (int i = 0; i < 5; ++i) {
        const int c = i * 256 + tid;
        if (c < 1024) {
            const int row = c >> 4, off = c & 15;
            CP_ASYNC16(swb + row * 288 + off * 16, wv + row * 64 + off * 4);
        } else if (c < 1152) {
            const int c2 = c - 1024;
            const int row = c2 >> 4, off = c2 & 15;
            CP_ASYNC16(swb + (64 + row) * 288 + off * 16, wq + row * 64 + off * 4);
        } else {
            const int c3 = c - 1152;
            const int row = c3 >> 4, off = c3 & 15;
            CP_ASYNC16(swb + (72 + row) * 288 + off * 16, wk + row * 64 + off * 4);
        }
    }
    CP_COMMIT();

    float acc[2][5][4];
    #pragma unroll
    for (int mt = 0; mt < 4; ++mt) {
        const float bA = __ldg(bv + mt * 16 + g);
        const float bB = __ldg(bv + mt * 16 + 8 + g);
        #pragma unroll
        for (int n2 = 0; n2 < 2; ++n2) {
            acc[n2][mt][0] = bA; acc[n2][mt][1] = bA;
            acc[n2][mt][2] = bB; acc[n2][mt][3] = bB;
        }
    }
    {
        const float bA = __ldg(bq + g);
        const float bB = __ldg(bk + g);
        #pragma unroll
        for (int n2 = 0; n2 < 2; ++n2) {
            acc[n2][4][0] = bA; acc[n2][4][1] = bA;
            acc[n2][4][2] = bB; acc[n2][4][3] = bB;
        }
    }

    CP_WAIT0();
    __syncthreads();

    const uint32_t waddr0 = swb + (uint32_t)g * 288 + (uint32_t)t4 * 8;
    const uint32_t xaddr0 = smb + tile * SX_TILE + (uint32_t)(2 * t4) * 272
                          + (uint32_t)((wg * 2) * 8 + g) * 4;
    #pragma unroll
    for (int kt = 0; kt < 8; ++kt) {
        uint32_t wa[5][4];
        #pragma unroll
        for (int mt = 0; mt < 5; ++mt) {
            LDS64(wa[mt][0], wa[mt][2], waddr0 + (uint32_t)(mt * 16) * 288 + kt * 32);
            LDS64(wa[mt][1], wa[mt][3], waddr0 + (uint32_t)(mt * 16 + 8) * 288 + kt * 32);
        }
        #pragma unroll
        for (int mt = 0; mt < 5; ++mt) {
            #pragma unroll
            for (int e = 0; e < 4; ++e) wa[mt][e] = tf32c(__uint_as_float(wa[mt][e]));
        }
        #pragma unroll
        for (int n2 = 0; n2 < 2; ++n2) {
            uint32_t b0, b1;
            LDS32(b0, xaddr0 + kt * (8 * 272) + n2 * 32);
            LDS32(b1, xaddr0 + kt * (8 * 272) + n2 * 32 + 272);
            b0 = tf32c(__uint_as_float(b0));
            b1 = tf32c(__uint_as_float(b1));
            #pragma unroll
            for (int mt = 0; mt < 5; ++mt)
                MMAT32(acc[n2][mt], wa[mt][0], wa[mt][1], wa[mt][2], wa[mt][3], b0, b1);
        }
    }

    const int kslot = 2 * (g & 3) + (g >> 2);
    #pragma unroll
    for (int n2 = 0; n2 < 2; ++n2) {
        const int px = tile * 64 + (wg * 2 + n2) * 8 + 2 * t4;
        #pragma unroll
        for (int mt = 0; mt < 4; ++mt) {
            const int coA = mt * 16 + g;
            const int coB = coA + 8;
            *(uint32_t*)(g_Vh + (size_t)b * CC * NN + (size_t)coA * NN + n0 + px) =
                packh(acc[n2][mt][0], acc[n2][mt][1]);
            *(uint32_t*)(g_Vh + (size_t)b * CC * NN + (size_t)coB * NN + n0 + px) =
                packh(acc[n2][mt][2], acc[n2][mt][3]);
        }
        const size_t base0 = ((size_t)b * NN + n0 + px) * CQ;
        const size_t base1 = base0 + CQ;
        g_Q[base0 + g] = acc[n2][4][0] * LOG2E;
        g_Q[base1 + g] = acc[n2][4][1] * LOG2E;
        g_Kt[base0 + kslot] = tf32c(acc[n2][4][2]);
        g_Kt[base1 + kslot] = tf32c(acc[n2][4][3]);
    }
}

// ---------------------------------------------------------------------------
// Kernel 2: fused attention — round-12 config (occ 3, NSPLIT 4, f32 partials),
// l via f16 HADD2 pair-sums (off the tensor pipe) + per-tile f32 fold.
// Block = 128 thr = 4 warps x 32 query rows. grid (32, 8, 4) = 1024 CTAs.
// ---------------------------------------------------------------------------
__global__ void __launch_bounds__(128, 3) attn_kernel()
{
    __shared__ __align__(16) char smraw[6144 + 3 * 8192];

    const int tid  = threadIdx.x;
    const int lane = tid & 31;
    const int w    = tid >> 5;
    const int g    = lane >> 2;
    const int t4   = lane & 3;
    const int b    = blockIdx.y;
    const int s    = blockIdx.z;
    const int ibase = blockIdx.x * 128 + w * 32;

    const uint32_t smb = smem_u32(smraw);

    // Q A-fragments for 2 m-tiles
    const float* Qb = g_Q + (size_t)b * NN * CQ;
    uint32_t qa[2][4];
    #pragma unroll
    for (int mt = 0; mt < 2; ++mt) {
        const float* q0p = Qb + (size_t)(ibase + mt * 16 + g) * CQ;
        const float* q1p = Qb + (size_t)(ibase + mt * 16 + g + 8) * CQ;
        qa[mt][0] = tf32c(q0p[t4]);
        qa[mt][1] = tf32c(q1p[t4]);
        qa[mt][2] = tf32c(q0p[t4 + 4]);
        qa[mt][3] = tf32c(q1p[t4 + 4]);
    }

    // K staging (split-shifted)
    const uint32_t* Ksrc = g_Kt + (size_t)b * NN * CQ + (size_t)s * KEYS_PER_SPLIT * CQ
                         + (size_t)(tid >> 1) * 8 + (tid & 1) * 4;
    const uint32_t kdst = smb + (uint32_t)(tid >> 1) * 32 + (uint32_t)(tid & 1) * 16;

    // V staging (split-shifted)
    const char* Vgb = (const char*)(g_Vh + (size_t)b * CC * NN);
    const uint32_t voff0 = (uint32_t)(tid >> 3) * (NN * 2) + (uint32_t)(tid & 7) * 16
                         + (uint32_t)s * (KEYS_PER_SPLIT * 2);
    const uint32_t vdst0 = smb + 6144 + (uint32_t)(tid >> 3) * 128
                         + (uint32_t)(((tid & 7) ^ ((tid >> 3) & 7)) << 4);

    // Score B-fragment LDS address
    const uint32_t kfrag0 = smb + (uint32_t)(lane >> 2) * 32 + (uint32_t)t4 * 8;

    // V ldmatrix addresses
    const int mat = lane >> 3, mrow = lane & 7, m01 = mat & 1;
    const uint32_t vbase0 = smb + 6144 + (uint32_t)((mat >> 1) * 8 + mrow) * 128;

    // Prologue: tiles 0, 1 of this split
    #pragma unroll
    for (int t = 0; t < 2; ++t) {
        CP_ASYNC16(kdst + t * 2048, Ksrc + (size_t)t * KT * CQ);
        #pragma unroll
        for (int r = 0; r < 4; ++r)
            CP_ASYNC16(vdst0 + r * 2048 + t * 8192, Vgb + voff0 + r * 131072 + t * 128);
        CP_COMMIT();
    }

    float acc[2][8][4];
    #pragma unroll
    for (int mt = 0; mt < 2; ++mt)
        #pragma unroll
        for (int nb = 0; nb < 8; ++nb)
            #pragma unroll
            for (int e = 0; e < 4; ++e) acc[mt][nb][e] = 0.f;
    float lsum[4] = {0.f, 0.f, 0.f, 0.f};   // [mt*2 + rowhalf], f32
    uint32_t ksoff = 0, vsoff = 0;

    #pragma unroll 1
    for (int t = 0; t < TILES_PER_SPLIT; ++t) {
        CP_WAIT1();
        __syncthreads();

        // Prefetch tile t+2
        {
            const int tc = t + 2;
            uint32_t ks2 = ksoff + 4096;  if (ks2 >= 6144)  ks2 -= 6144;
            uint32_t vs2 = vsoff + 16384; if (vs2 >= 24576) vs2 -= 24576;
            if (tc < TILES_PER_SPLIT) {
                CP_ASYNC16(kdst + ks2, Ksrc + (size_t)tc * KT * CQ);
                #pragma unroll
                for (int r = 0; r < 4; ++r)
                    CP_ASYNC16(vdst0 + r * 2048 + vs2,
                               Vgb + voff0 + r * 131072 + (size_t)tc * 128);
            }
            CP_COMMIT();
        }

        // Per-tile f16 row-sum accumulators (values <= ~450, safe in f16)
        uint32_t lh[4] = {0u, 0u, 0u, 0u};

        #pragma unroll
        for (int kt = 0; kt < 4; ++kt) {
            uint32_t b00, b01, b10, b11;
            LDS64(b00, b01, kfrag0 + ksoff + (uint32_t)(2 * kt) * 256);
            LDS64(b10, b11, kfrag0 + ksoff + (uint32_t)(2 * kt) * 256 + 256);

            float p[2][2][4];
            #pragma unroll
            for (int mt = 0; mt < 2; ++mt) {
                MMAT32_Z(p[mt][0], qa[mt][0], qa[mt][1], qa[mt][2], qa[mt][3], b00, b01);
                MMAT32_Z(p[mt][1], qa[mt][0], qa[mt][1], qa[mt][2], qa[mt][3], b10, b11);
            }

            uint32_t a[2][4];
            #pragma unroll
            for (int mt = 0; mt < 2; ++mt) {
                a[mt][0] = ex2h2(packh(p[mt][0][0], p[mt][0][1]));
                a[mt][1] = ex2h2(packh(p[mt][0][2], p[mt][0][3]));
                a[mt][2] = ex2h2(packh(p[mt][1][0], p[mt][1][1]));
                a[mt][3] = ex2h2(packh(p[mt][1][2], p[mt][1][3]));
            }

            // l row-sums on the fma pipe: a[mt][0]/[2] are row g (ntiles 0/1),
            // a[mt][1]/[3] are row g+8.
            #pragma unroll
            for (int mt = 0; mt < 2; ++mt) {
                lh[2 * mt + 0] = hadd2(lh[2 * mt + 0], hadd2(a[mt][0], a[mt][2]));
                lh[2 * mt + 1] = hadd2(lh[2 * mt + 1], hadd2(a[mt][1], a[mt][3]));
            }

            const uint32_t term = ((uint32_t)((2 * kt + m01) ^ mrow)) << 4;
            uint32_t vb[16];
            #pragma unroll
            for (int c = 0; c < 4; ++c)
                LDSM4(vb[4 * c + 0], vb[4 * c + 1], vb[4 * c + 2], vb[4 * c + 3],
                      vbase0 + vsoff + c * 2048 + term);
            #pragma unroll
            for (int mt = 0; mt < 2; ++mt)
                #pragma unroll
                for (int nb = 0; nb < 8; ++nb)
                    MMAH16(acc[mt][nb], a[mt][0], a[mt][1], a[mt][2], a[mt][3],
                           vb[2 * nb], vb[2 * nb + 1]);
        }

        // Fold this tile's f16 sums into f32
        #pragma unroll
        for (int r = 0; r < 4; ++r) {
            const float2 f = __half22float2(*(const __half2*)&lh[r]);
            lsum[r] += f.x + f.y;
        }

        ksoff += 2048; if (ksoff == 6144)  ksoff = 0;
        vsoff += 8192; if (vsoff == 24576) vsoff = 0;
    }

    // Reduce l over the 4 lanes of each quad (keys split across t4)
    #pragma unroll
    for (int r = 0; r < 4; ++r) {
        lsum[r] += __shfl_xor_sync(0xFFFFFFFFu, lsum[r], 1);
        lsum[r] += __shfl_xor_sync(0xFFFFFFFFu, lsum[r], 2);
    }

    // Write unnormalized f32 partials
    float* Pb = g_P + ((size_t)(s * BB + b) * CC) * NN;
    #pragma unroll
    for (int mt = 0; mt < 2; ++mt) {
        const int rA = ibase + mt * 16 + g;
        const int rB = rA + 8;
        #pragma unroll
        for (int nb = 0; nb < 8; ++nb) {
            const int c = nb * 8 + 2 * t4;
            Pb[(size_t)c * NN + rA]       = acc[mt][nb][0];
            Pb[(size_t)(c + 1) * NN + rA] = acc[mt][nb][1];
            Pb[(size_t)c * NN + rB]       = acc[mt][nb][2];
            Pb[(size_t)(c + 1) * NN + rB] = acc[mt][nb][3];
        }
    }
    if (t4 == 0) {
        float* Lb = g_L + (size_t)(s * BB + b) * NN;
        #pragma unroll
        for (int mt = 0; mt < 2; ++mt) {
            Lb[ibase + mt * 16 + g]     = lsum[2 * mt + 0];
            Lb[ibase + mt * 16 + g + 8] = lsum[2 * mt + 1];
        }
    }
}

// ---------------------------------------------------------------------------
// Kernel 3: combine split-K f32 partials. out = sum_s P_s / sum_s L_s.
// ---------------------------------------------------------------------------
__global__ void __launch_bounds__(256) reduce_kernel(float* __restrict__ out)
{
    const int idx = blockIdx.x * 256 + threadIdx.x;
    const int i4  = idx & 1023;
    const int bc  = idx >> 10;
    const int b   = bc >> 6;

    const float4* P4 = (const float4*)g_P;
    const float4* L4 = (const float4*)g_L;

    float4 ps = make_float4(0.f, 0.f, 0.f, 0.f);
    float4 ls = make_float4(0.f, 0.f, 0.f, 0.f);
    #pragma unroll
    for (int s = 0; s < NSPLIT; ++s) {
        const float4 p = P4[(size_t)(s * (BB * CC) + bc) * 1024 + i4];
        const float4 l = L4[(size_t)(s * BB + b) * 1024 + i4];
        ps.x += p.x; ps.y += p.y; ps.z += p.z; ps.w += p.w;
        ls.x += l.x; ls.y += l.y; ls.z += l.z; ls.w += l.w;
    }
    float4 o;
    o.x = ps.x / ls.x;
    o.y = ps.y / ls.y;
    o.z = ps.z / ls.z;
    o.w = ps.w / ls.w;
    ((float4*)out)[(size_t)bc * 1024 + i4] = o;
}

// ---------------------------------------------------------------------------
extern "C" void kernel_launch(void* const* d_in, const int* in_sizes, int n_in,
                              void* d_out, int out_size)
{
    const float* x  = (const float*)d_in[0];
    const float* wq = (const float*)d_in[1];
    const float* bq = (const float*)d_in[2];
    const float* wk = (const float*)d_in[3];
    const float* bk = (const float*)d_in[4];
    const float* wv = (const float*)d_in[5];
    const float* bv = (const float*)d_in[6];
    float* out = (float*)d_out;

    cudaFuncSetAttribute(proj_kernel, cudaFuncAttributeMaxDynamicSharedMemorySize, SMEM_PROJ);

    dim3 pgrid(NN / 128, BB);
    proj_kernel<<<pgrid, 256, SMEM_PROJ>>>(x, wq, bq, wk, bk, wv, bv);

    dim3 agrid(NN / 128, BB, NSPLIT);
    attn_kernel<<<agrid, 128>>>();

    reduce_kernel<<<2048, 256>>>(out);
}

// round 16
// speedup vs baseline: 1.1526x; 1.0325x over previous
#include <cuda_runtime.h>
#include <cuda_fp16.h>
#include <cstdint>

#define BB 8
#define CC 64
#define CQ 8
#define NN 4096
#define KT 64
#define NSPLIT 4
#define KEYS_PER_SPLIT (NN / NSPLIT)          // 1024
#define TILES_PER_SPLIT (KEYS_PER_SPLIT / KT) // 16
#define LOG2E 1.4426950408889634f

// Device scratch (allocation-free rule)
__device__ float    g_Q[BB * NN * CQ];           // [b][n][cq] f32, pre-scaled by log2e
__device__ uint32_t g_Kt[BB * NN * CQ];          // [b][n]: 8 tf32 bits, pair-permuted (c,c+4)
__device__ __half   g_Vh[BB * CC * NN];          // [b][c][n] fp16 (V^T)
__device__ uint32_t g_P[NSPLIT * BB * 32 * NN];  // [s][b][cp][i] half2 = chans (2cp,2cp+1) (16MB)
__device__ float    g_L[NSPLIT * BB * NN];       // [s][b][i] partial row sums (f32)

// ---------------------------------------------------------------------------
// PTX helpers (baseline compute_103-safe)
// ---------------------------------------------------------------------------
__device__ __forceinline__ uint32_t smem_u32(const void* p) {
    uint32_t a;
    asm("{ .reg .u64 t; cvta.to.shared.u64 t, %1; cvt.u32.u64 %0, t; }" : "=r"(a) : "l"(p));
    return a;
}
__device__ __forceinline__ uint32_t packh(float lo, float hi) {   // f16x2 {hi|lo}
    uint32_t r;
    asm("cvt.rn.f16x2.f32 %0, %1, %2;" : "=r"(r) : "f"(hi), "f"(lo));
    return r;
}
__device__ __forceinline__ uint32_t ex2h2(uint32_t x) {           // packed f16x2 exp2
    uint32_t y;
    asm("ex2.approx.f16x2 %0, %1;" : "=r"(y) : "r"(x));
    return y;
}
__device__ __forceinline__ uint32_t hadd2(uint32_t a, uint32_t b) {
    uint32_t r;
    asm("add.f16x2 %0, %1, %2;" : "=r"(r) : "r"(a), "r"(b));
    return r;
}
__device__ __forceinline__ uint32_t tf32c(float f) {
    uint32_t r;
    asm("cvt.rna.tf32.f32 %0, %1;" : "=r"(r) : "f"(f));
    return r;
}
#define LDSM4(r0, r1, r2, r3, a) \
    asm volatile("ldmatrix.sync.aligned.m8n8.x4.shared.b16 {%0,%1,%2,%3}, [%4];" \
        : "=r"(r0), "=r"(r1), "=r"(r2), "=r"(r3) : "r"(a))
#define LDS64(r0, r1, a) \
    asm volatile("ld.shared.v2.u32 {%0,%1}, [%2];" : "=r"(r0), "=r"(r1) : "r"(a))
#define LDS32(r0, a) \
    asm volatile("ld.shared.u32 %0, [%1];" : "=r"(r0) : "r"(a))

#define CP_ASYNC16(dst, src) \
    asm volatile("cp.async.ca.shared.global [%0], [%1], 16;" :: "r"(dst), "l"(src) : "memory")
#define CP_COMMIT() asm volatile("cp.async.commit_group;" ::: "memory")
#define CP_WAIT0()  asm volatile("cp.async.wait_group 0;" ::: "memory")
#define CP_WAIT1()  asm volatile("cp.async.wait_group 1;" ::: "memory")

// m16n8k8 tf32 MMA, C = 0
#define MMAT32_Z(d, a0, a1, a2, a3, b0, b1) \
    asm volatile("mma.sync.aligned.m16n8k8.row.col.f32.tf32.tf32.f32 " \
        "{%0,%1,%2,%3}, {%4,%5,%6,%7}, {%8,%9}, {%10,%10,%10,%10};" \
        : "=f"((d)[0]), "=f"((d)[1]), "=f"((d)[2]), "=f"((d)[3]) \
        : "r"(a0), "r"(a1), "r"(a2), "r"(a3), "r"(b0), "r"(b1), "f"(0.f))
// m16n8k8 tf32 MMA, accumulate in place
#define MMAT32(d, a0, a1, a2, a3, b0, b1) \
    asm volatile("mma.sync.aligned.m16n8k8.row.col.f32.tf32.tf32.f32 " \
        "{%0,%1,%2,%3}, {%4,%5,%6,%7}, {%8,%9}, {%0,%1,%2,%3};" \
        : "+f"((d)[0]), "+f"((d)[1]), "+f"((d)[2]), "+f"((d)[3]) \
        : "r"(a0), "r"(a1), "r"(a2), "r"(a3), "r"(b0), "r"(b1))
// m16n8k16 fp16 MMA (f32 accum), accumulate in place
#define MMAH16(d, a0, a1, a2, a3, b0, b1) \
    asm volatile("mma.sync.aligned.m16n8k16.row.col.f32.f16.f16.f32 " \
        "{%0,%1,%2,%3}, {%4,%5,%6,%7}, {%8,%9}, {%0,%1,%2,%3};" \
        : "+f"((d)[0]), "+f"((d)[1]), "+f"((d)[2]), "+f"((d)[3]) \
        : "r"(a0), "r"(a1), "r"(a2), "r"(a3), "r"(b0), "r"(b1))

// ---------------------------------------------------------------------------
// Kernel 1: projections on tensor cores (tf32) — round-15 version (9.2us).
// ---------------------------------------------------------------------------
#define SX_TILE 17408
#define SW_OFF  (2 * SX_TILE)
#define SMEM_PROJ (SW_OFF + 80 * 288)

__global__ void __launch_bounds__(256, 3) proj_kernel(
    const float* __restrict__ x,
    const float* __restrict__ wq, const float* __restrict__ bq,
    const float* __restrict__ wk, const float* __restrict__ bk,
    const float* __restrict__ wv, const float* __restrict__ bv)
{
    extern __shared__ __align__(16) char smp[];

    const int tid  = threadIdx.x;
    const int lane = tid & 31;
    const int w    = tid >> 5;
    const int wg   = w & 3;
    const int tile = w >> 2;
    const int g    = lane >> 2;
    const int t4   = lane & 3;
    const int b    = blockIdx.y;
    const int n0   = blockIdx.x * 128;

    const uint32_t smb = smem_u32(smp);
    const uint32_t swb = smb + SW_OFF;

    const float* xb = x + (size_t)b * CC * NN + n0;
    #pragma unroll
    for (int i = 0; i < 8; ++i) {
        const int c = i * 256 + tid;
        const int tl = c >> 10, wi = c & 1023;
        const int row = wi >> 4, off = wi & 15;
        CP_ASYNC16(smb + tl * SX_TILE + row * 272 + off * 16,
                   xb + (size_t)row * NN + tl * 64 + off * 4);
    }
    #pragma unroll
    for (int i = 0; i < 5; ++i) {
        const int c = i * 256 + tid;
        if (c < 1024) {
            const int row = c >> 4, off = c & 15;
            CP_ASYNC16(swb + row * 288 + off * 16, wv + row * 64 + off * 4);
        } else if (c < 1152) {
            const int c2 = c - 1024;
            const int row = c2 >> 4, off = c2 & 15;
            CP_ASYNC16(swb + (64 + row) * 288 + off * 16, wq + row * 64 + off * 4);
        } else {
            const int c3 = c - 1152;
            const int row = c3 >> 4, off = c3 & 15;
            CP_ASYNC16(swb + (72 + row) * 288 + off * 16, wk + row * 64 + off * 4);
        }
    }
    CP_COMMIT();

    float acc[2][5][4];
    #pragma unroll
    for (int mt = 0; mt < 4; ++mt) {
        const float bA = __ldg(bv + mt * 16 + g);
        const float bB = __ldg(bv + mt * 16 + 8 + g);
        #pragma unroll
        for (int n2 = 0; n2 < 2; ++n2) {
            acc[n2][mt][0] = bA; acc[n2][mt][1] = bA;
            acc[n2][mt][2] = bB; acc[n2][mt][3] = bB;
        }
    }
    {
        const float bA = __ldg(bq + g);
        const float bB = __ldg(bk + g);
        #pragma unroll
        for (int n2 = 0; n2 < 2; ++n2) {
            acc[n2][4][0] = bA; acc[n2][4][1] = bA;
            acc[n2][4][2] = bB; acc[n2][4][3] = bB;
        }
    }

    CP_WAIT0();
    __syncthreads();

    const uint32_t waddr0 = swb + (uint32_t)g * 288 + (uint32_t)t4 * 8;
    const uint32_t xaddr0 = smb + tile * SX_TILE + (uint32_t)(2 * t4) * 272
                          + (uint32_t)((wg * 2) * 8 + g) * 4;
    #pragma unroll
    for (int kt = 0; kt < 8; ++kt) {
        uint32_t wa[5][4];
        #pragma unroll
        for (int mt = 0; mt < 5; ++mt) {
            LDS64(wa[mt][0], wa[mt][2], waddr0 + (uint32_t)(mt * 16) * 288 + kt * 32);
            LDS64(wa[mt][1], wa[mt][3], waddr0 + (uint32_t)(mt * 16 + 8) * 288 + kt * 32);
        }
        #pragma unroll
        for (int mt = 0; mt < 5; ++mt) {
            #pragma unroll
            for (int e = 0; e < 4; ++e) wa[mt][e] = tf32c(__uint_as_float(wa[mt][e]));
        }
        #pragma unroll
        for (int n2 = 0; n2 < 2; ++n2) {
            uint32_t b0, b1;
            LDS32(b0, xaddr0 + kt * (8 * 272) + n2 * 32);
            LDS32(b1, xaddr0 + kt * (8 * 272) + n2 * 32 + 272);
            b0 = tf32c(__uint_as_float(b0));
            b1 = tf32c(__uint_as_float(b1));
            #pragma unroll
            for (int mt = 0; mt < 5; ++mt)
                MMAT32(acc[n2][mt], wa[mt][0], wa[mt][1], wa[mt][2], wa[mt][3], b0, b1);
        }
    }

    const int kslot = 2 * (g & 3) + (g >> 2);
    #pragma unroll
    for (int n2 = 0; n2 < 2; ++n2) {
        const int px = tile * 64 + (wg * 2 + n2) * 8 + 2 * t4;
        #pragma unroll
        for (int mt = 0; mt < 4; ++mt) {
            const int coA = mt * 16 + g;
            const int coB = coA + 8;
            *(uint32_t*)(g_Vh + (size_t)b * CC * NN + (size_t)coA * NN + n0 + px) =
                packh(acc[n2][mt][0], acc[n2][mt][1]);
            *(uint32_t*)(g_Vh + (size_t)b * CC * NN + (size_t)coB * NN + n0 + px) =
                packh(acc[n2][mt][2], acc[n2][mt][3]);
        }
        const size_t base0 = ((size_t)b * NN + n0 + px) * CQ;
        const size_t base1 = base0 + CQ;
        g_Q[base0 + g] = acc[n2][4][0] * LOG2E;
        g_Q[base1 + g] = acc[n2][4][1] * LOG2E;
        g_Kt[base0 + kslot] = tf32c(acc[n2][4][2]);
        g_Kt[base1 + kslot] = tf32c(acc[n2][4][3]);
    }
}

// ---------------------------------------------------------------------------
// Kernel 2: fused attention — round-15 body; epilogue writes PACKED f16x2
// partials in paired-channel layout [s][b][cp][i] (32 STG.32 vs 64).
// Block = 128 thr = 4 warps x 32 query rows. grid (32, 8, 4) = 1024 CTAs.
// ---------------------------------------------------------------------------
__global__ void __launch_bounds__(128, 3) attn_kernel()
{
    __shared__ __align__(16) char smraw[6144 + 3 * 8192];

    const int tid  = threadIdx.x;
    const int lane = tid & 31;
    const int w    = tid >> 5;
    const int g    = lane >> 2;
    const int t4   = lane & 3;
    const int b    = blockIdx.y;
    const int s    = blockIdx.z;
    const int ibase = blockIdx.x * 128 + w * 32;

    const uint32_t smb = smem_u32(smraw);

    // Q A-fragments for 2 m-tiles
    const float* Qb = g_Q + (size_t)b * NN * CQ;
    uint32_t qa[2][4];
    #pragma unroll
    for (int mt = 0; mt < 2; ++mt) {
        const float* q0p = Qb + (size_t)(ibase + mt * 16 + g) * CQ;
        const float* q1p = Qb + (size_t)(ibase + mt * 16 + g + 8) * CQ;
        qa[mt][0] = tf32c(q0p[t4]);
        qa[mt][1] = tf32c(q1p[t4]);
        qa[mt][2] = tf32c(q0p[t4 + 4]);
        qa[mt][3] = tf32c(q1p[t4 + 4]);
    }

    // K staging (split-shifted)
    const uint32_t* Ksrc = g_Kt + (size_t)b * NN * CQ + (size_t)s * KEYS_PER_SPLIT * CQ
                         + (size_t)(tid >> 1) * 8 + (tid & 1) * 4;
    const uint32_t kdst = smb + (uint32_t)(tid >> 1) * 32 + (uint32_t)(tid & 1) * 16;

    // V staging (split-shifted)
    const char* Vgb = (const char*)(g_Vh + (size_t)b * CC * NN);
    const uint32_t voff0 = (uint32_t)(tid >> 3) * (NN * 2) + (uint32_t)(tid & 7) * 16
                         + (uint32_t)s * (KEYS_PER_SPLIT * 2);
    const uint32_t vdst0 = smb + 6144 + (uint32_t)(tid >> 3) * 128
                         + (uint32_t)(((tid & 7) ^ ((tid >> 3) & 7)) << 4);

    // Score B-fragment LDS address
    const uint32_t kfrag0 = smb + (uint32_t)(lane >> 2) * 32 + (uint32_t)t4 * 8;

    // V ldmatrix addresses
    const int mat = lane >> 3, mrow = lane & 7, m01 = mat & 1;
    const uint32_t vbase0 = smb + 6144 + (uint32_t)((mat >> 1) * 8 + mrow) * 128;

    // Prologue: tiles 0, 1 of this split
    #pragma unroll
    for (int t = 0; t < 2; ++t) {
        CP_ASYNC16(kdst + t * 2048, Ksrc + (size_t)t * KT * CQ);
        #pragma unroll
        for (int r = 0; r < 4; ++r)
            CP_ASYNC16(vdst0 + r * 2048 + t * 8192, Vgb + voff0 + r * 131072 + t * 128);
        CP_COMMIT();
    }

    float acc[2][8][4];
    #pragma unroll
    for (int mt = 0; mt < 2; ++mt)
        #pragma unroll
        for (int nb = 0; nb < 8; ++nb)
            #pragma unroll
            for (int e = 0; e < 4; ++e) acc[mt][nb][e] = 0.f;
    float lsum[4] = {0.f, 0.f, 0.f, 0.f};
    uint32_t ksoff = 0, vsoff = 0;

    #pragma unroll 1
    for (int t = 0; t < TILES_PER_SPLIT; ++t) {
        CP_WAIT1();
        __syncthreads();

        // Prefetch tile t+2
        {
            const int tc = t + 2;
            uint32_t ks2 = ksoff + 4096;  if (ks2 >= 6144)  ks2 -= 6144;
            uint32_t vs2 = vsoff + 16384; if (vs2 >= 24576) vs2 -= 24576;
            if (tc < TILES_PER_SPLIT) {
                CP_ASYNC16(kdst + ks2, Ksrc + (size_t)tc * KT * CQ);
                #pragma unroll
                for (int r = 0; r < 4; ++r)
                    CP_ASYNC16(vdst0 + r * 2048 + vs2,
                               Vgb + voff0 + r * 131072 + (size_t)tc * 128);
            }
            CP_COMMIT();
        }

        // Per-tile f16 row-sum accumulators (values <= ~450, safe in f16)
        uint32_t lh[4] = {0u, 0u, 0u, 0u};

        #pragma unroll
        for (int kt = 0; kt < 4; ++kt) {
            uint32_t b00, b01, b10, b11;
            LDS64(b00, b01, kfrag0 + ksoff + (uint32_t)(2 * kt) * 256);
            LDS64(b10, b11, kfrag0 + ksoff + (uint32_t)(2 * kt) * 256 + 256);

            float p[2][2][4];
            #pragma unroll
            for (int mt = 0; mt < 2; ++mt) {
                MMAT32_Z(p[mt][0], qa[mt][0], qa[mt][1], qa[mt][2], qa[mt][3], b00, b01);
                MMAT32_Z(p[mt][1], qa[mt][0], qa[mt][1], qa[mt][2], qa[mt][3], b10, b11);
            }

            uint32_t a[2][4];
            #pragma unroll
            for (int mt = 0; mt < 2; ++mt) {
                a[mt][0] = ex2h2(packh(p[mt][0][0], p[mt][0][1]));
                a[mt][1] = ex2h2(packh(p[mt][0][2], p[mt][0][3]));
                a[mt][2] = ex2h2(packh(p[mt][1][0], p[mt][1][1]));
                a[mt][3] = ex2h2(packh(p[mt][1][2], p[mt][1][3]));
            }

            // l row-sums on the fma pipe
            #pragma unroll
            for (int mt = 0; mt < 2; ++mt) {
                lh[2 * mt + 0] = hadd2(lh[2 * mt + 0], hadd2(a[mt][0], a[mt][2]));
                lh[2 * mt + 1] = hadd2(lh[2 * mt + 1], hadd2(a[mt][1], a[mt][3]));
            }

            const uint32_t term = ((uint32_t)((2 * kt + m01) ^ mrow)) << 4;
            uint32_t vb[16];
            #pragma unroll
            for (int c = 0; c < 4; ++c)
                LDSM4(vb[4 * c + 0], vb[4 * c + 1], vb[4 * c + 2], vb[4 * c + 3],
                      vbase0 + vsoff + c * 2048 + term);
            #pragma unroll
            for (int mt = 0; mt < 2; ++mt)
                #pragma unroll
                for (int nb = 0; nb < 8; ++nb)
                    MMAH16(acc[mt][nb], a[mt][0], a[mt][1], a[mt][2], a[mt][3],
                           vb[2 * nb], vb[2 * nb + 1]);
        }

        // Fold this tile's f16 sums into f32
        #pragma unroll
        for (int r = 0; r < 4; ++r) {
            const float2 f = __half22float2(*(const __half2*)&lh[r]);
            lsum[r] += f.x + f.y;
        }

        ksoff += 2048; if (ksoff == 6144)  ksoff = 0;
        vsoff += 8192; if (vsoff == 24576) vsoff = 0;
    }

    // Reduce l over the 4 lanes of each quad
    #pragma unroll
    for (int r = 0; r < 4; ++r) {
        lsum[r] += __shfl_xor_sync(0xFFFFFFFFu, lsum[r], 1);
        lsum[r] += __shfl_xor_sync(0xFFFFFFFFu, lsum[r], 2);
    }

    // Write packed f16x2 partials: [cp][i], cp = (nb*8 + 2*t4)/2 = nb*4 + t4
    uint32_t* Pb = g_P + (size_t)(s * BB + b) * 32 * NN;
    #pragma unroll
    for (int mt = 0; mt < 2; ++mt) {
        const int rA = ibase + mt * 16 + g;
        const int rB = rA + 8;
        #pragma unroll
        for (int nb = 0; nb < 8; ++nb) {
            const int cp = nb * 4 + t4;
            Pb[(size_t)cp * NN + rA] = packh(acc[mt][nb][0], acc[mt][nb][1]);
            Pb[(size_t)cp * NN + rB] = packh(acc[mt][nb][2], acc[mt][nb][3]);
        }
    }
    if (t4 == 0) {
        float* Lb = g_L + (size_t)(s * BB + b) * NN;
        #pragma unroll
        for (int mt = 0; mt < 2; ++mt) {
            Lb[ibase + mt * 16 + g]     = lsum[2 * mt + 0];
            Lb[ibase + mt * 16 + g + 8] = lsum[2 * mt + 1];
        }
    }
}

// ---------------------------------------------------------------------------
// Kernel 3: combine split-K packed-f16x2 partials.
// Thread handles 4 pixels of one cp row -> two f32x4 output rows (chans 2cp, 2cp+1).
// 8b x 32cp x 1024 chunks = 262144 threads -> 1024 blocks x 256.
// ---------------------------------------------------------------------------
__global__ void __launch_bounds__(256) reduce_kernel(float* __restrict__ out)
{
    const int idx = blockIdx.x * 256 + threadIdx.x;
    const int i4  = idx & 1023;                // 4096/4 pixel chunks
    const int bcp = idx >> 10;                 // b*32 + cp
    const int b   = bcp >> 5;
    const int cp  = bcp & 31;

    float p0[4] = {0.f, 0.f, 0.f, 0.f};       // channel 2cp
    float p1[4] = {0.f, 0.f, 0.f, 0.f};       // channel 2cp+1
    float ls[4] = {0.f, 0.f, 0.f, 0.f};

    #pragma unroll
    for (int s = 0; s < NSPLIT; ++s) {
        const uint4 pw = *(const uint4*)(g_P + ((size_t)(s * BB + b) * 32 + cp) * NN + i4 * 4);
        const uint32_t pk[4] = {pw.x, pw.y, pw.z, pw.w};
        #pragma unroll
        for (int j = 0; j < 4; ++j) {
            const float2 f = __half22float2(*(const __half2*)&pk[j]);
            p0[j] += f.x;
            p1[j] += f.y;
        }
        const float4 l = *(const float4*)(g_L + (size_t)(s * BB + b) * NN + i4 * 4);
        ls[0] += l.x; ls[1] += l.y; ls[2] += l.z; ls[3] += l.w;
    }

    float* ob = out + (size_t)b * CC * NN;
    *(float4*)(ob + (size_t)(2 * cp) * NN + i4 * 4) =
        make_float4(p0[0] / ls[0], p0[1] / ls[1], p0[2] / ls[2], p0[3] / ls[3]);
    *(float4*)(ob + (size_t)(2 * cp + 1) * NN + i4 * 4) =
        make_float4(p1[0] / ls[0], p1[1] / ls[1], p1[2] / ls[2], p1[3] / ls[3]);
}

// ---------------------------------------------------------------------------
extern "C" void kernel_launch(void* const* d_in, const int* in_sizes, int n_in,
                              void* d_out, int out_size)
{
    const float* x  = (const float*)d_in[0];
    const float* wq = (const float*)d_in[1];
    const float* bq = (const float*)d_in[2];
    const float* wk = (const float*)d_in[3];
    const float* bk = (const float*)d_in[4];
    const float* wv = (const float*)d_in[5];
    const float* bv = (const float*)d_in[6];
    float* out = (float*)d_out;

    cudaFuncSetAttribute(proj_kernel, cudaFuncAttributeMaxDynamicSharedMemorySize, SMEM_PROJ);

    dim3 pgrid(NN / 128, BB);
    proj_kernel<<<pgrid, 256, SMEM_PROJ>>>(x, wq, bq, wk, bk, wv, bv);

    dim3 agrid(NN / 128, BB, NSPLIT);
    attn_kernel<<<agrid, 128>>>();

    reduce_kernel<<<1024, 256>>>(out);
}